// round 12
// baseline (speedup 1.0000x reference)
#include <cuda_runtime.h>
#include <math.h>
#include <stdint.h>

// Problem constants (fixed shapes per reference)
#define BB 32
#define PP 16384
#define TT 64
#define NC 64                 // pred chunks per batch
#define CP (PP / NC)          // 256 preds per chunk
#define NSUB 32               // pred sub-streams
#define NT 8                  // targets per thread
#define TPB 256               // threads per block = (TT/NT) * NSUB = 8*32
#define PPT (CP / NSUB)       // 8 preds per thread
#define SENT 0x7fffffff

// Scratch (no allocations allowed). Zero-initialized at module load; every
// launch leaves all of these back at zero so graph replays are deterministic.
__device__ unsigned long long g_best[BB * TT];   // (trunc_r_bits<<32) | (~p)
__device__ float        g_conf_part[BB * NC];
__device__ float        g_per[BB];
__device__ unsigned int g_arrive[BB];
__device__ unsigned int g_done;

__device__ __forceinline__ float softplus_f(float x) {
    return fmaxf(x, 0.0f) + log1pf(expf(-fabsf(x)));
}

// ONE kernel: per (batch, chunk) IoU scan with fan-in finalize.
// Ranking trick: r = inter / (pa + ga) is a strictly increasing function of
// iou = inter / (pa + ga - inter), so argmax by r == argmax by iou, and
// (iou > 0.5) == (r > 1/3).
__global__ void __launch_bounds__(TPB, 4) iou_kernel(
    const float* __restrict__ preds, const float* __restrict__ targets,
    float* __restrict__ out)
{
    const int c = blockIdx.x;
    const int b = blockIdx.y;
    const int tid = threadIdx.x;
    const int tg  = tid >> 5;    // 0..7  -> targets tg*8 .. tg*8+7
    const int sub = tid & 31;    // 0..31 -> pred sub-stream

    __shared__ float    sraw[CP * 5];     // staged raw preds
    __shared__ float4   sbox[CP];         // (x1, y1, x2, y2)
    __shared__ float    sarea[CP];
    __shared__ unsigned s_key[TT][NSUB + 1];
    __shared__ float    s_w[TPB / 32];
    __shared__ bool     s_last;

    // Stage this chunk's preds (256 x 5 floats = 5KB), coalesced float4.
    {
        const float4* src = (const float4*)(preds + ((size_t)b * PP + (size_t)c * CP) * 5);
        float4* dst = (float4*)sraw;
        #pragma unroll
        for (int i = tid; i < CP * 5 / 4; i += TPB) dst[i] = src[i];
    }

    // Load this thread's 8 targets into registers (overlaps with staging)
    float gx1[NT], gy1[NT], gx2[NT], gy2[NT], ga[NT];
    const float* tb = targets + (size_t)b * TT * 4;
    #pragma unroll
    for (int k = 0; k < NT; k++) {
        int t = tg * NT + k;
        float x = __ldg(tb + t * 4 + 0);
        float y = __ldg(tb + t * 4 + 1);
        float w = __ldg(tb + t * 4 + 2);
        float h = __ldg(tb + t * 4 + 3);
        gx1[k] = x; gy1[k] = y; gx2[k] = x + w; gy2[k] = y + h; ga[k] = w * h;
    }

    __syncthreads();

    // Transform pass: one thread per pred row -> SoA + derived values.
    float conf_acc;
    {
        int r = tid;  // CP == TPB
        float x = sraw[r * 5 + 0];
        float y = sraw[r * 5 + 1];
        float w = sraw[r * 5 + 2];
        float h = sraw[r * 5 + 3];
        float l = sraw[r * 5 + 4];
        sbox[r]  = make_float4(x, y, x + w, y + h);
        sarea[r] = w * h;
        conf_acc = softplus_f(l);
    }

    // Running best as 32-bit key: high 28 bits = r float bits (r >= 0 so u32
    // ordering == float ordering), low 4 bits = PPT-1-i (iteration index
    // within this sub-stream) so equal truncated r pick the SMALLER i.
    // pl = i*32 + sub, so (key desc, then sub asc) == ascending global pred
    // index: jnp.argmax first-max semantics at 28-bit compare granularity.
    unsigned bkey[NT];
    #pragma unroll
    for (int k = 0; k < NT; k++) bkey[k] = 0u;

    __syncthreads();

    #pragma unroll
    for (int i = 0; i < PPT; i++) {
        const int pl = sub + i * NSUB;
        float4 pb = sbox[pl];
        float  pa = sarea[pl];
        const unsigned idxb = (unsigned)(PPT - 1 - i);   // fits in 4 bits
        #pragma unroll
        for (int k = 0; k < NT; k++) {
            float xa = fmaxf(gx1[k], pb.x);
            float xb = fminf(gx2[k], pb.z);
            float ya = fmaxf(gy1[k], pb.y);
            float yb = fminf(gy2[k], pb.w);
            float w  = fmaxf(xb - xa, 0.0f);
            float h  = fmaxf(yb - ya, 0.0f);
            float inter = w * h;
            float S = pa + ga[k];                  // > 0 for this data
            float r = __fdividef(inter, S);        // monotone proxy for iou
            unsigned key = (__float_as_uint(r) & 0xFFFFFFF0u) | idxb;
            bkey[k] = umax(bkey[k], key);
        }
    }

    // Reduce across the 32 sub-streams per target; track winning column s
    // so we can reconstruct pl = i*32 + s.
    #pragma unroll
    for (int k = 0; k < NT; k++) {
        s_key[tg * NT + k][sub] = bkey[k];
    }
    __syncthreads();
    if (tid < TT) {
        unsigned best = 0u; int bs = 0;
        #pragma unroll
        for (int s = 0; s < NSUB; s++) {
            unsigned k2 = s_key[tid][s];
            if (k2 > best) { best = k2; bs = s; }  // strict: equal keys keep smaller s
        }
        int i  = (PPT - 1) - (int)(best & 0xFu);
        int p  = c * CP + (bs + i * NSUB);
        unsigned long long gkey =
            ((unsigned long long)(best & 0xFFFFFFF0u) << 32) |
            (unsigned long long)(0xffffffffu - (unsigned)p);
        atomicMax(&g_best[b * TT + tid], gkey);
    }

    // Conf partial: warp-shuffle reduce -> g_conf_part[b*NC + c]
    {
        float v = conf_acc;
        #pragma unroll
        for (int o = 16; o > 0; o >>= 1) v += __shfl_down_sync(0xffffffffu, v, o);
        if ((tid & 31) == 0) s_w[tid >> 5] = v;
    }
    __syncthreads();
    if (tid == 0) {
        float s = 0.0f;
        #pragma unroll
        for (int i = 0; i < TPB / 32; i++) s += s_w[i];
        g_conf_part[b * NC + c] = s;
        // Release this block's contributions, then arrive.
        __threadfence();
        unsigned prev = atomicAdd(&g_arrive[b], 1u);
        s_last = (prev == NC - 1);
    }
    __syncthreads();
    if (!s_last) return;

    // ---- This is the last block of batch b: finalize batch b ----
    __threadfence();  // acquire all other blocks' g_best / g_conf_part writes
    if (tid == 0) g_arrive[b] = 0u;  // reset for next replay

    __shared__ int   vals[TT];
    __shared__ int   sorted_[TT];

    int val = SENT;
    if (tid < TT) {
        unsigned long long key = g_best[b * TT + tid];
        g_best[b * TT + tid] = 0ull;  // reset for next replay
        float bi = __uint_as_float((unsigned)(key >> 32));
        int   bx = (int)(0xffffffffu - (unsigned)key);
        // flag: iou > 0.5  <=>  r > 1/3
        val = (bi > (1.0f / 3.0f)) ? bx : SENT;
        vals[tid] = val;
    }
    __syncthreads();

    // Dedupe: keep lowest-t occurrence of each positive index
    if (tid < TT && val != SENT) {
        bool dup = false;
        for (int j = 0; j < tid; j++) dup |= (vals[j] == val);
        if (dup) val = SENT;
    }
    __syncthreads();
    if (tid < TT) vals[tid] = val;
    __syncthreads();

    // Rank-sort ascending (sentinels last, stable)
    if (tid < TT) {
        int rank = 0;
        for (int j = 0; j < TT; j++) {
            int vj = vals[j];
            rank += (vj < val) || (vj == val && j < tid);
        }
        sorted_[rank] = val;
    }
    int n = __syncthreads_count(tid < TT && val != SENT);

    float sq = 0.0f, corr = 0.0f, base = 0.0f;
    if (tid < TT) {
        if (tid < n) {
            int p = sorted_[tid];
            const float* pp = preds + ((size_t)b * PP + p) * 5;
            const float* tg2 = targets + ((size_t)b * TT + tid) * 4;
            #pragma unroll
            for (int k = 0; k < 4; k++) {
                float d = __ldg(pp + k) - __ldg(tg2 + k);
                sq += d * d;
            }
            corr = -__ldg(pp + 4);  // softplus(-l) - softplus(l) == -l
        }
        base = g_conf_part[b * NC + tid];  // NC == TT == 64
    }

    // Block reduce (only first 2 warps have nonzero values)
    #pragma unroll
    for (int o = 16; o > 0; o >>= 1) {
        sq   += __shfl_down_sync(0xffffffffu, sq,   o);
        corr += __shfl_down_sync(0xffffffffu, corr, o);
        base += __shfl_down_sync(0xffffffffu, base, o);
    }
    __shared__ float r0[2], r1[2], r2[2];
    if (tid == 0)  { r0[0] = sq; r1[0] = corr; r2[0] = base; }
    if (tid == 32) { r0[1] = sq; r1[1] = corr; r2[1] = base; }
    __syncthreads();

    if (tid == 0) {
        float conf = (r2[0] + r2[1] + r1[0] + r1[1]) * (1.0f / (float)PP);
        float bbox = (r0[0] + r0[1]) / fmaxf((float)n * 4.0f, 1.0f);
        g_per[b] = (n > 0) ? (bbox + conf) : 0.0f;
        __threadfence();
        unsigned prev = atomicAdd(&g_done, 1u);
        s_last = (prev == BB - 1);
    }
    __syncthreads();
    if (!s_last) return;

    // ---- Globally last batch finisher: deterministic final sum ----
    __threadfence();
    if (tid < 32) {
        float v = g_per[tid];
        #pragma unroll
        for (int o = 16; o > 0; o >>= 1) v += __shfl_down_sync(0xffffffffu, v, o);
        if (tid == 0) { out[0] = v * (1.0f / (float)BB); g_done = 0u; }
    }
}

extern "C" void kernel_launch(void* const* d_in, const int* in_sizes, int n_in,
                              void* d_out, int out_size)
{
    const float* preds   = (const float*)d_in[0];
    const float* targets = (const float*)d_in[1];
    float* out = (float*)d_out;

    iou_kernel<<<dim3(NC, BB), TPB>>>(preds, targets, out);
}

// round 13
// speedup vs baseline: 1.1614x; 1.1614x over previous
#include <cuda_runtime.h>
#include <math.h>
#include <stdint.h>

// Problem constants (fixed shapes per reference)
#define BB 32
#define PP 16384
#define TT 64
#define NC 64                 // pred chunks per batch
#define CP (PP / NC)          // 256 preds per chunk
#define NSUB 16               // pred sub-streams
#define NT 4                  // targets per thread
#define TPB 256               // threads per block = (TT/NT) * NSUB
#define PPT (CP / NSUB)       // 16 preds per thread
#define SENT 0x7fffffff

// Scratch (no allocations allowed). Zero-initialized at module load; every
// launch leaves all of these back at zero so graph replays are deterministic.
__device__ unsigned long long g_best[BB * TT];   // (trunc_r_bits<<32) | (~p)
__device__ float        g_conf_part[BB * NC];
__device__ float        g_per[BB];
__device__ unsigned int g_arrive[BB];
__device__ unsigned int g_done;

__device__ __forceinline__ float softplus_f(float x) {
    return fmaxf(x, 0.0f) + log1pf(expf(-fabsf(x)));
}

// ONE kernel: per (batch, chunk) IoU scan with fan-in finalize.
// Ranking trick: r = inter / (pa + ga) is strictly increasing in iou, so
// argmax by r == argmax by iou and (iou > 0.5) == (r > 1/3).
// Sign trick: only dx is clamped; if dy < 0 then inter <= 0, r <= 0, and the
// float sign bit makes the key NEGATIVE as s32 — it loses every signed max
// against the 0-initialized accumulator, which is exactly the clamp semantics.
__global__ void __launch_bounds__(TPB, 4) iou_kernel(
    const float* __restrict__ preds, const float* __restrict__ targets,
    float* __restrict__ out)
{
    const int c = blockIdx.x;
    const int b = blockIdx.y;
    const int tid = threadIdx.x;
    const int tg  = tid >> 4;    // 0..15 -> targets tg*4 .. tg*4+3
    const int sub = tid & 15;    // 0..15 -> pred sub-stream

    __shared__ float    sraw[CP * 5];     // staged raw preds
    __shared__ float4   sbox[CP];         // (x1, y1, x2, y2)
    __shared__ float    sarea[CP];
    __shared__ int      s_key[TT][NSUB + 1];
    __shared__ float    s_w[TPB / 32];
    __shared__ bool     s_last;

    // Stage this chunk's preds (256 x 5 floats = 5KB), coalesced float4.
    {
        const float4* src = (const float4*)(preds + ((size_t)b * PP + (size_t)c * CP) * 5);
        float4* dst = (float4*)sraw;
        #pragma unroll
        for (int i = tid; i < CP * 5 / 4; i += TPB) dst[i] = src[i];
    }

    // Load this thread's 4 targets into registers (overlaps with staging)
    float gx1[NT], gy1[NT], gx2[NT], gy2[NT], ga[NT];
    const float* tb = targets + (size_t)b * TT * 4;
    #pragma unroll
    for (int k = 0; k < NT; k++) {
        int t = tg * NT + k;
        float x = __ldg(tb + t * 4 + 0);
        float y = __ldg(tb + t * 4 + 1);
        float w = __ldg(tb + t * 4 + 2);
        float h = __ldg(tb + t * 4 + 3);
        gx1[k] = x; gy1[k] = y; gx2[k] = x + w; gy2[k] = y + h; ga[k] = w * h;
    }

    __syncthreads();

    // Transform pass: one thread per pred row -> SoA + derived values.
    float conf_acc;
    {
        int r = tid;  // CP == TPB
        float x = sraw[r * 5 + 0];
        float y = sraw[r * 5 + 1];
        float w = sraw[r * 5 + 2];
        float h = sraw[r * 5 + 3];
        float l = sraw[r * 5 + 4];
        sbox[r]  = make_float4(x, y, x + w, y + h);
        sarea[r] = w * h;
        conf_acc = softplus_f(l);
    }

    // Running best as SIGNED 32-bit key: high 28 bits = r float bits (for
    // r >= 0, s32 ordering == float ordering; r < 0 keys are negative and
    // always lose), low 4 bits = PPT-1-i so equal truncated r pick the
    // SMALLER i. pl = i*16 + sub, so (key desc, then sub asc) == ascending
    // global pred index: jnp.argmax first-max semantics.
    int bkey[NT];
    #pragma unroll
    for (int k = 0; k < NT; k++) bkey[k] = 0;

    __syncthreads();

    #pragma unroll
    for (int i = 0; i < PPT; i++) {
        const int pl = sub + i * NSUB;
        float4 pb = sbox[pl];
        float  pa = sarea[pl];
        const unsigned idxb = (unsigned)(PPT - 1 - i);   // 4 bits, literal
        #pragma unroll
        for (int k = 0; k < NT; k++) {
            float dx = fminf(gx2[k], pb.z) - fmaxf(gx1[k], pb.x);
            float dy = fminf(gy2[k], pb.w) - fmaxf(gy1[k], pb.y);
            float w  = fmaxf(dx, 0.0f);
            float inter = w * dy;                  // <= 0 when dy <= 0
            float S = pa + ga[k];                  // > 0 for this data
            float r = __fdividef(inter, S);        // sign follows inter
            int key = (int)((__float_as_uint(r) & 0xFFFFFFF0u) | idxb);
            bkey[k] = max(bkey[k], key);           // signed IMNMX
        }
    }

    // Reduce across the 16 sub-streams per target; track winning column s
    // so we can reconstruct pl = i*16 + s.
    #pragma unroll
    for (int k = 0; k < NT; k++) {
        s_key[tg * NT + k][sub] = bkey[k];
    }
    __syncthreads();
    if (tid < TT) {
        int best = 0; int bs = 0;
        #pragma unroll
        for (int s = 0; s < NSUB; s++) {
            int k2 = s_key[tid][s];
            if (k2 > best) { best = k2; bs = s; }  // strict: equal keys keep smaller s
        }
        int i  = (PPT - 1) - (best & 0xF);
        int p  = c * CP + (bs + i * NSUB);
        unsigned long long gkey =
            ((unsigned long long)((unsigned)best & 0xFFFFFFF0u) << 32) |
            (unsigned long long)(0xffffffffu - (unsigned)p);
        atomicMax(&g_best[b * TT + tid], gkey);
    }

    // Conf partial: warp-shuffle reduce -> g_conf_part[b*NC + c]
    {
        float v = conf_acc;
        #pragma unroll
        for (int o = 16; o > 0; o >>= 1) v += __shfl_down_sync(0xffffffffu, v, o);
        if ((tid & 31) == 0) s_w[tid >> 5] = v;
    }
    __syncthreads();
    if (tid == 0) {
        float s = 0.0f;
        #pragma unroll
        for (int i = 0; i < TPB / 32; i++) s += s_w[i];
        g_conf_part[b * NC + c] = s;
        // Release this block's contributions, then arrive.
        __threadfence();
        unsigned prev = atomicAdd(&g_arrive[b], 1u);
        s_last = (prev == NC - 1);
    }
    __syncthreads();
    if (!s_last) return;

    // ---- This is the last block of batch b: finalize batch b ----
    __threadfence();  // acquire all other blocks' g_best / g_conf_part writes
    if (tid == 0) g_arrive[b] = 0u;  // reset for next replay

    __shared__ int   vals[TT];
    __shared__ int   sorted_[TT];

    int val = SENT;
    if (tid < TT) {
        unsigned long long key = g_best[b * TT + tid];
        g_best[b * TT + tid] = 0ull;  // reset for next replay
        float bi = __uint_as_float((unsigned)(key >> 32));
        int   bx = (int)(0xffffffffu - (unsigned)key);
        // flag: iou > 0.5  <=>  r > 1/3
        val = (bi > (1.0f / 3.0f)) ? bx : SENT;
        vals[tid] = val;
    }
    __syncthreads();

    // Dedupe: keep lowest-t occurrence of each positive index
    if (tid < TT && val != SENT) {
        bool dup = false;
        for (int j = 0; j < tid; j++) dup |= (vals[j] == val);
        if (dup) val = SENT;
    }
    __syncthreads();
    if (tid < TT) vals[tid] = val;
    __syncthreads();

    // Rank-sort ascending (sentinels last, stable)
    if (tid < TT) {
        int rank = 0;
        for (int j = 0; j < TT; j++) {
            int vj = vals[j];
            rank += (vj < val) || (vj == val && j < tid);
        }
        sorted_[rank] = val;
    }
    int n = __syncthreads_count(tid < TT && val != SENT);

    float sq = 0.0f, corr = 0.0f, base = 0.0f;
    if (tid < TT) {
        if (tid < n) {
            int p = sorted_[tid];
            const float* pp = preds + ((size_t)b * PP + p) * 5;
            const float* tg2 = targets + ((size_t)b * TT + tid) * 4;
            #pragma unroll
            for (int k = 0; k < 4; k++) {
                float d = __ldg(pp + k) - __ldg(tg2 + k);
                sq += d * d;
            }
            corr = -__ldg(pp + 4);  // softplus(-l) - softplus(l) == -l
        }
        base = g_conf_part[b * NC + tid];  // NC == TT == 64
    }

    // Block reduce (only first 2 warps have nonzero values)
    #pragma unroll
    for (int o = 16; o > 0; o >>= 1) {
        sq   += __shfl_down_sync(0xffffffffu, sq,   o);
        corr += __shfl_down_sync(0xffffffffu, corr, o);
        base += __shfl_down_sync(0xffffffffu, base, o);
    }
    __shared__ float r0[2], r1[2], r2[2];
    if (tid == 0)  { r0[0] = sq; r1[0] = corr; r2[0] = base; }
    if (tid == 32) { r0[1] = sq; r1[1] = corr; r2[1] = base; }
    __syncthreads();

    if (tid == 0) {
        float conf = (r2[0] + r2[1] + r1[0] + r1[1]) * (1.0f / (float)PP);
        float bbox = (r0[0] + r0[1]) / fmaxf((float)n * 4.0f, 1.0f);
        g_per[b] = (n > 0) ? (bbox + conf) : 0.0f;
        __threadfence();
        unsigned prev = atomicAdd(&g_done, 1u);
        s_last = (prev == BB - 1);
    }
    __syncthreads();
    if (!s_last) return;

    // ---- Globally last batch finisher: deterministic final sum ----
    __threadfence();
    if (tid < 32) {
        float v = g_per[tid];
        #pragma unroll
        for (int o = 16; o > 0; o >>= 1) v += __shfl_down_sync(0xffffffffu, v, o);
        if (tid == 0) { out[0] = v * (1.0f / (float)BB); g_done = 0u; }
    }
}

extern "C" void kernel_launch(void* const* d_in, const int* in_sizes, int n_in,
                              void* d_out, int out_size)
{
    const float* preds   = (const float*)d_in[0];
    const float* targets = (const float*)d_in[1];
    float* out = (float*)d_out;

    iou_kernel<<<dim3(NC, BB), TPB>>>(preds, targets, out);
}